// round 11
// baseline (speedup 1.0000x reference)
#include <cuda_runtime.h>
#include <cuda_fp16.h>
#include <cstdint>

#define NV   200000
#define KOFF 27
#define CA   64
#define CB   128
#define NBLK 256
#define EPSF 1e-5f

// ---------------- device scratch ----------------
__device__ __half g_f0h[(NV + 1) * CA];      // fp16(feats), zero dummy row
__device__ __half g_h1h[(NV + 1) * CB];      // fp16 conv1 out, zero dummy row
__device__ int    g_g2 [KOFF * NV];          // inverse map, stores gidx+1 (0 = invalid)
__device__ __half g_w1h[KOFF * CB * CA];     // fp16( bn1_scale[c] * w1[k][c][n] ) as [k][n][c]
__device__ __half g_w2h[KOFF * CB * CB];     // fp16( bn2_scale[c] * w2[k][c][n] ) as [k][n][c]
__device__ __half g_tb1[CB * 64];            // bias-trick B for conv1: [n][kk], kk<27 used
__device__ __half g_tb2[CB * 64];            // bias-trick B for conv2
__device__ __half g_wnh[CB * 64];            // fp16(w_nin) as [n][c]
__device__ float  g_psum[NBLK * CB];
__device__ float  g_psq [NBLK * CB];
__device__ float  g_sc[2][CB];
__device__ float  g_sh[2][CB];

// ---------------- helpers ----------------
__device__ __forceinline__ uint32_t smem_u32(const void* p) {
    uint32_t a;
    asm("{ .reg .u64 t; cvta.to.shared.u64 t, %1; cvt.u32.u64 %0, t; }" : "=r"(a) : "l"(p));
    return a;
}
__device__ __forceinline__ void cpa16(uint32_t s, const void* g) {
    asm volatile("cp.async.cg.shared.global [%0], [%1], 16;" :: "r"(s), "l"(g));
}
__device__ __forceinline__ void cpa_commit() {
    asm volatile("cp.async.commit_group;" ::: "memory");
}
__device__ __forceinline__ void cpa_wait1() { asm volatile("cp.async.wait_group 1;" ::: "memory"); }
__device__ __forceinline__ void cpa_wait0() { asm volatile("cp.async.wait_group 0;" ::: "memory"); }
__device__ __forceinline__ void sts16(uint32_t addr, uint4 v) {
    asm volatile("st.shared.v4.b32 [%0], {%1,%2,%3,%4};"
                 :: "r"(addr), "r"(v.x), "r"(v.y), "r"(v.z), "r"(v.w) : "memory");
}
__device__ __forceinline__ void ldsm4(uint32_t* d, uint32_t addr) {
    asm volatile("ldmatrix.sync.aligned.m8n8.x4.shared.b16 {%0,%1,%2,%3}, [%4];"
                 : "=r"(d[0]), "=r"(d[1]), "=r"(d[2]), "=r"(d[3]) : "r"(addr));
}
__device__ __forceinline__ void mma16(float* c, const uint32_t* a, const uint32_t* b) {
    asm volatile(
        "mma.sync.aligned.m16n8k16.row.col.f32.f16.f16.f32 "
        "{%0,%1,%2,%3}, {%4,%5,%6,%7}, {%8,%9}, {%0,%1,%2,%3};"
        : "+f"(c[0]), "+f"(c[1]), "+f"(c[2]), "+f"(c[3])
        : "r"(a[0]), "r"(a[1]), "r"(a[2]), "r"(a[3]), "r"(b[0]), "r"(b[1]));
}

// ---------------- BN stats: fp32 input (feats) ----------------
template <int C>
__global__ void k_bn_partial(const float* __restrict__ x) {
    const int C4 = C / 4;
    float4 s = make_float4(0.f, 0.f, 0.f, 0.f);
    float4 q = make_float4(0.f, 0.f, 0.f, 0.f);
    const int tot = NV * C4;
    const int tid = threadIdx.x;
    for (int i = blockIdx.x * 256 + tid; i < tot; i += NBLK * 256) {
        float4 v = ((const float4*)x)[i];
        s.x += v.x; s.y += v.y; s.z += v.z; s.w += v.w;
        q.x += v.x * v.x; q.y += v.y * v.y; q.z += v.z * v.z; q.w += v.w * v.w;
    }
    __shared__ float4 sh[256];
    sh[tid] = s;
    __syncthreads();
    if (tid < C4) {
        float4 a = sh[tid];
        for (int o = C4; o < 256; o += C4) {
            float4 b = sh[tid + o];
            a.x += b.x; a.y += b.y; a.z += b.z; a.w += b.w;
        }
        ((float4*)(g_psum + blockIdx.x * C))[tid] = a;
    }
    __syncthreads();
    sh[tid] = q;
    __syncthreads();
    if (tid < C4) {
        float4 a = sh[tid];
        for (int o = C4; o < 256; o += C4) {
            float4 b = sh[tid + o];
            a.x += b.x; a.y += b.y; a.z += b.z; a.w += b.w;
        }
        ((float4*)(g_psq + blockIdx.x * C))[tid] = a;
    }
}

// ---------------- BN stats: fp16 input (h1h), C = 128 ----------------
__global__ void k_bn_partial_h(const __half* __restrict__ x) {
    float s[8], q[8];
    #pragma unroll
    for (int t = 0; t < 8; ++t) { s[t] = 0.f; q[t] = 0.f; }
    const int tid = threadIdx.x;
    const int tot = NV * 16;
    for (int i = blockIdx.x * 256 + tid; i < tot; i += NBLK * 256) {
        uint4 v = ((const uint4*)x)[i];
        const uint32_t u[4] = {v.x, v.y, v.z, v.w};
        #pragma unroll
        for (int p = 0; p < 4; ++p) {
            float2 f = __half22float2(*(const __half2*)&u[p]);
            s[2 * p] += f.x; s[2 * p + 1] += f.y;
            q[2 * p] += f.x * f.x; q[2 * p + 1] += f.y * f.y;
        }
    }
    __shared__ float sh[256 * 8];
    #pragma unroll
    for (int t = 0; t < 8; ++t) sh[tid * 8 + t] = s[t];
    __syncthreads();
    if (tid < 128) {
        int cb = tid >> 3, ci = tid & 7;
        float a = 0.f;
        #pragma unroll
        for (int j = 0; j < 16; ++j) a += sh[(cb + 16 * j) * 8 + ci];
        g_psum[blockIdx.x * 128 + tid] = a;
    }
    __syncthreads();
    #pragma unroll
    for (int t = 0; t < 8; ++t) sh[tid * 8 + t] = q[t];
    __syncthreads();
    if (tid < 128) {
        int cb = tid >> 3, ci = tid & 7;
        float a = 0.f;
        #pragma unroll
        for (int j = 0; j < 16; ++j) a += sh[(cb + 16 * j) * 8 + ci];
        g_psq[blockIdx.x * 128 + tid] = a;
    }
}

template <int C, int IDX>
__global__ void k_bn_finalize(const float* __restrict__ gamma, const float* __restrict__ beta) {
    const int tid = threadIdx.x;   // blockDim = 4*C
    const int c = tid % C;
    const int qd = tid / C;
    float s = 0.f, s2 = 0.f;
    #pragma unroll 8
    for (int b = qd * (NBLK / 4); b < (qd + 1) * (NBLK / 4); ++b) {
        s  += g_psum[b * C + c];
        s2 += g_psq [b * C + c];
    }
    __shared__ float sha[4 * CB], shb[4 * CB];
    sha[tid] = s; shb[tid] = s2;
    __syncthreads();
    if (qd == 0) {
        s  = sha[c] + sha[C + c] + sha[2 * C + c] + sha[3 * C + c];
        s2 = shb[c] + shb[C + c] + shb[2 * C + c] + shb[3 * C + c];
        float mean = s / (float)NV;
        float var  = s2 / (float)NV - mean * mean;
        float a = rsqrtf(var + EPSF) * gamma[c];
        g_sc[IDX][c] = a;
        g_sh[IDX][c] = beta[c] - mean * a;
    }
}

// ---------------- prep1 ----------------
#define NB_F0  12500          // NV*64/4/256
#define NB_W1  864            // 27*128*64/256
#define NB_TB  32             // 128*64/256
#define NB_MI  1
#define NB_MAP 21094          // ceil(27*NV/256)
__global__ void k_prep1(const float* __restrict__ feats, const float* __restrict__ w1,
                        const int* __restrict__ gidx, const int* __restrict__ sidx) {
    const int b = blockIdx.x;
    const int tid = threadIdx.x;
    if (b < NB_F0) {
        int i = b * 256 + tid;
        float4 v = ((const float4*)feats)[i];
        ((__half2*)g_f0h)[2 * i]     = __floats2half2_rn(v.x, v.y);
        ((__half2*)g_f0h)[2 * i + 1] = __floats2half2_rn(v.z, v.w);
    } else if (b < NB_F0 + NB_W1) {
        int i = (b - NB_F0) * 256 + tid;       // 221184
        int k = i >> 13;
        int rem = i & 8191;
        int n = rem >> 6, c = rem & 63;
        g_w1h[i] = __float2half_rn(g_sc[0][c] * w1[(k * 64 + c) * 128 + n]);
    } else if (b < NB_F0 + NB_W1 + NB_TB) {
        int i = (b - NB_F0 - NB_W1) * 256 + tid;  // 8192
        int n = i >> 6, kk = i & 63;
        float acc = 0.f;
        if (kk < KOFF)
            for (int c = 0; c < 64; ++c)
                acc += g_sh[0][c] * w1[(kk * 64 + c) * 128 + n];
        g_tb1[i] = __float2half_rn(acc);
    } else if (b < NB_F0 + NB_W1 + NB_TB + NB_MI) {
        if (tid < 32)              ((__half2*)(g_f0h + NV * CA))[tid] = __half2half2(__ushort_as_half(0));
        if (tid >= 32 && tid < 96) ((__half2*)(g_h1h + NV * CB))[tid - 32] = __half2half2(__ushort_as_half(0));
    } else {
        int j = (b - NB_F0 - NB_W1 - NB_TB - NB_MI) * 256 + tid;
        if (j < KOFF * NV) {
            int s = sidx[j];
            if (s < NV) {
                int k = j / NV;
                g_g2[k * NV + s] = gidx[j] + 1;
            }
        }
    }
}

// ---------------- prep2 ----------------
#define NB_W2  1728           // 27*128*128/256
__global__ void k_prep2(const float* __restrict__ w2, const float* __restrict__ wnin) {
    const int b = blockIdx.x;
    const int tid = threadIdx.x;
    if (b < NB_W2) {
        int i = b * 256 + tid;                 // 442368
        int k = i >> 14;
        int rem = i & 16383;
        int n = rem >> 7, c = rem & 127;
        g_w2h[i] = __float2half_rn(g_sc[1][c] * w2[(k * 128 + c) * 128 + n]);
    } else if (b < NB_W2 + NB_TB) {
        int i = (b - NB_W2) * 256 + tid;
        int n = i >> 6, kk = i & 63;
        float acc = 0.f;
        if (kk < KOFF)
            for (int c = 0; c < 128; ++c)
                acc += g_sh[1][c] * w2[(kk * 128 + c) * 128 + n];
        g_tb2[i] = __float2half_rn(acc);
    } else {
        int i = (b - NB_W2 - NB_TB) * 256 + tid;  // 8192
        int n = i >> 6, c = i & 63;
        g_wnh[i] = __float2half_rn(wnin[c * 128 + n]);
    }
}

// ---------------- fp16 warp-MMA gather-GEMM conv: SMALL CTAs ----------------
// CTA: 128 thr / 4 warps; tile M=64 x N=128; warp: rows (wid&1)*32, cols (wid>>1)*64.
// 4 CTAs/SM = 4 independent barrier domains per SMSP (overlap across CTAs).
// K chunks of 64; 2-stage cp.async pipeline; XOR-swizzled smem.
// NV = 64 * 3125 exactly -> no row guards needed.
template <int CIN, bool SKIP, bool OUTH>
__global__ void __launch_bounds__(128, 4)
k_conv(const __half* __restrict__ src, const __half* __restrict__ wt,
       const __half* __restrict__ tb, void* __restrict__ dstv) {
    extern __shared__ __align__(16) char smraw[];
    // stage: A (64x64h = 8KB) at +0 | B (128x64h = 16KB) at +8192; stage stride 24576
    int* sIdx = (int*)(smraw + 2 * 24576);   // [27][64]
    const uint32_t tile0 = smem_u32(smraw);

    const int tid  = threadIdx.x;
    const int lane = tid & 31;
    const int wid  = tid >> 5;
    const int g    = lane >> 2;
    const int tig  = lane & 3;
    const int row0 = blockIdx.x * 64;
    const int warpRow = (wid & 1) * 32;
    const int warpCol = (wid >> 1) * 64;

    constexpr int MAIN = KOFF * (CIN / 64);
    constexpr int CH   = MAIN + (SKIP ? 1 : 0) + 1;

    for (int i = tid; i < KOFF * 64; i += 128) {
        int k = i >> 6, r = i & 63;
        int v = g_g2[k * NV + row0 + r];
        sIdx[i] = v ? (v - 1) : NV;
    }
    __syncthreads();

    const int lr  = tid >> 3;     // 0..15 row group for loads
    const int sub = tid & 7;      // 16B unit within 128B row

    auto issue = [&](int s) {
        const uint32_t aB = tile0 + (uint32_t)(s & 1) * 24576u;
        const uint32_t bB = aB + 8192u;
        if (s < MAIN) {
            const int k27 = (CIN == 64) ? s : (s >> 1);
            const int kb  = (CIN == 64) ? 0 : ((s & 1) << 6);
            #pragma unroll
            for (int j = 0; j < 4; ++j) {
                int r = lr + j * 16;
                int gg = sIdx[(k27 << 6) + r];
                uint32_t off = (uint32_t)((r << 7) + ((sub ^ (r & 7)) << 4));
                cpa16(aB + off, src + (size_t)gg * CIN + kb + sub * 8);
            }
            const __half* bs = wt + ((size_t)k27 * 128) * CIN + kb;
            #pragma unroll
            for (int j = 0; j < 8; ++j) {
                int n = lr + j * 16;
                uint32_t off = (uint32_t)((n << 7) + ((sub ^ (n & 7)) << 4));
                cpa16(bB + off, bs + (size_t)n * CIN + sub * 8);
            }
        } else if (SKIP && s == MAIN) {
            #pragma unroll
            for (int j = 0; j < 4; ++j) {
                int r = lr + j * 16;
                uint32_t off = (uint32_t)((r << 7) + ((sub ^ (r & 7)) << 4));
                cpa16(aB + off, g_f0h + (size_t)(row0 + r) * 64 + sub * 8);
            }
            #pragma unroll
            for (int j = 0; j < 8; ++j) {
                int n = lr + j * 16;
                uint32_t off = (uint32_t)((n << 7) + ((sub ^ (n & 7)) << 4));
                cpa16(bB + off, g_wnh + (size_t)n * 64 + sub * 8);
            }
        } else {
            // bias-mask chunk: A[r][kk] = (kk < 27 && gather valid) ? 1 : 0
            #pragma unroll
            for (int j = 0; j < 4; ++j) {
                int r = lr + j * 16;
                uint4 w;
                uint32_t* wp = (uint32_t*)&w;
                #pragma unroll
                for (int q = 0; q < 4; ++q) {
                    int kk0 = sub * 8 + 2 * q;
                    uint32_t h0 = (kk0 < KOFF && sIdx[(kk0 << 6) + r] != NV) ? 0x3C00u : 0u;
                    uint32_t h1 = (kk0 + 1 < KOFF && sIdx[((kk0 + 1) << 6) + r] != NV) ? 0x3C00u : 0u;
                    wp[q] = h0 | (h1 << 16);
                }
                uint32_t off = (uint32_t)((r << 7) + ((sub ^ (r & 7)) << 4));
                sts16(aB + off, w);
            }
            #pragma unroll
            for (int j = 0; j < 8; ++j) {
                int n = lr + j * 16;
                uint32_t off = (uint32_t)((n << 7) + ((sub ^ (n & 7)) << 4));
                cpa16(bB + off, tb + (size_t)n * 64 + sub * 8);
            }
        }
        cpa_commit();
    };

    float acc[2][8][4];
    #pragma unroll
    for (int mt = 0; mt < 2; ++mt)
        #pragma unroll
        for (int nt = 0; nt < 8; ++nt)
            #pragma unroll
            for (int q = 0; q < 4; ++q) acc[mt][nt][q] = 0.f;

    // ldmatrix lane address components
    const int s7 = lane & 7;
    const int rowA = warpRow + s7 + ((lane >> 3) & 1) * 8;
    const int uA   = lane >> 4;
    const int rowB = warpCol + s7 + (lane >> 4) * 8;
    const int uB   = (lane >> 3) & 1;

    issue(0);

    for (int s = 0; s < CH; ++s) {
        if (s + 1 < CH) { issue(s + 1); cpa_wait1(); }
        else            cpa_wait0();
        __syncthreads();

        const uint32_t aB = tile0 + (uint32_t)(s & 1) * 24576u;
        const uint32_t bB = aB + 8192u;
        const uint32_t pa0 = aB + ((uint32_t)rowA << 7);
        const uint32_t pa1 = aB + ((uint32_t)(rowA + 16) << 7);

        #pragma unroll
        for (int ks = 0; ks < 4; ++ks) {
            const int u0 = ks * 2;
            uint32_t a[2][4];
            const uint32_t aoff = (uint32_t)(((u0 + uA) ^ s7) << 4);
            ldsm4(a[0], pa0 + aoff);
            ldsm4(a[1], pa1 + aoff);
            const uint32_t boff = (uint32_t)(((u0 + uB) ^ s7) << 4);
            #pragma unroll
            for (int p = 0; p < 4; ++p) {
                uint32_t bfr[4];
                ldsm4(bfr, bB + ((uint32_t)(rowB + p * 16) << 7) + boff);
                mma16(acc[0][2 * p],     a[0], &bfr[0]);
                mma16(acc[0][2 * p + 1], a[0], &bfr[2]);
                mma16(acc[1][2 * p],     a[1], &bfr[0]);
                mma16(acc[1][2 * p + 1], a[1], &bfr[2]);
            }
        }
        __syncthreads();
    }

    // epilogue: direct register -> gmem (all rows in-range: NV % 64 == 0)
    #pragma unroll
    for (int mt = 0; mt < 2; ++mt) {
        int r0 = row0 + warpRow + mt * 16 + g;
        #pragma unroll
        for (int nt = 0; nt < 8; ++nt) {
            int col = warpCol + nt * 8 + 2 * tig;
            if (OUTH) {
                __half* dst = (__half*)dstv;
                *(__half2*)(dst + (size_t)r0 * CB + col) =
                    __floats2half2_rn(acc[mt][nt][0], acc[mt][nt][1]);
                *(__half2*)(dst + (size_t)(r0 + 8) * CB + col) =
                    __floats2half2_rn(acc[mt][nt][2], acc[mt][nt][3]);
            } else {
                float* dst = (float*)dstv;
                *(float2*)(dst + (size_t)r0 * CB + col) =
                    make_float2(acc[mt][nt][0], acc[mt][nt][1]);
                *(float2*)(dst + (size_t)(r0 + 8) * CB + col) =
                    make_float2(acc[mt][nt][2], acc[mt][nt][3]);
            }
        }
    }
}

// ---------------- launch ----------------
extern "C" void kernel_launch(void* const* d_in, const int* in_sizes, int n_in,
                              void* d_out, int out_size) {
    const float* feats     = (const float*)d_in[0];
    const float* w1        = (const float*)d_in[1];
    const float* w2        = (const float*)d_in[2];
    const float* w_nin     = (const float*)d_in[3];
    const float* bn1_gamma = (const float*)d_in[4];
    const float* bn1_beta  = (const float*)d_in[5];
    const float* bn2_gamma = (const float*)d_in[6];
    const float* bn2_beta  = (const float*)d_in[7];
    const int*   gidx      = (const int*)d_in[8];
    const int*   sidx      = (const int*)d_in[9];
    float*       out       = (float*)d_out;

    const int dynsm = 2 * 24576 + KOFF * 64 * 4;   // 49152 + 6912 = 56064 B -> 4 CTA/SM
    cudaFuncSetAttribute(k_conv<CA, false, true >, cudaFuncAttributeMaxDynamicSharedMemorySize, dynsm);
    cudaFuncSetAttribute(k_conv<CB, true,  false>, cudaFuncAttributeMaxDynamicSharedMemorySize, dynsm);

    __half *f0h, *h1h, *w1h, *w2h, *tb1, *tb2;
    cudaGetSymbolAddress((void**)&f0h, g_f0h);
    cudaGetSymbolAddress((void**)&h1h, g_h1h);
    cudaGetSymbolAddress((void**)&w1h, g_w1h);
    cudaGetSymbolAddress((void**)&w2h, g_w2h);
    cudaGetSymbolAddress((void**)&tb1, g_tb1);
    cudaGetSymbolAddress((void**)&tb2, g_tb2);

    const int grid = NV / 64;   // 3125

    k_bn_partial<CA><<<NBLK, 256>>>(feats);
    k_bn_finalize<CA, 0><<<1, 4 * CA>>>(bn1_gamma, bn1_beta);
    k_prep1<<<NB_F0 + NB_W1 + NB_TB + NB_MI + NB_MAP, 256>>>(feats, w1, gidx, sidx);
    // launch slot #4: conv1 (profiled)
    k_conv<CA, false, true><<<grid, 128, dynsm>>>(f0h, w1h, tb1, h1h);
    k_bn_partial_h<<<NBLK, 256>>>(h1h);
    k_bn_finalize<CB, 1><<<1, 4 * CB>>>(bn2_gamma, bn2_beta);
    k_prep2<<<NB_W2 + NB_TB + 32, 256>>>(w2, w_nin);
    k_conv<CB, true, false><<<grid, 128, dynsm>>>(h1h, w2h, tb2, out);
}

// round 12
// speedup vs baseline: 1.6027x; 1.6027x over previous
#include <cuda_runtime.h>
#include <cuda_fp16.h>
#include <cstdint>

#define NV   200000
#define NPAD 200064
#define TIL  1563
#define KOFF 27
#define CA   64
#define CB   128
#define NBLK 256
#define EPSF 1e-5f

// ---------------- device scratch ----------------
__device__ __half g_f0h[(NV + 1) * CA];
__device__ __half g_h1h[(NV + 1) * CB];
__device__ __half g_temp[(size_t)KOFF * NPAD * 128];  // fp16 partial rows, 1.38 GB
__device__ int    g_p2t[NPAD * 32];                   // per-output slot+1 per k (0=invalid)
__device__ float  g_base2[(size_t)NPAD * 128];        // skip GEMM out
__device__ __half g_w1h[KOFF * CB * CA];              // bn1-folded w1 [k][n][c]
__device__ __half g_w2h[KOFF * CB * CB];              // bn2-folded w2 [k][n][c]
__device__ float  g_tb1f[KOFF * 128];                 // bias row per (k,n)
__device__ float  g_tb2f[KOFF * 128];
__device__ __half g_wnh[CB * 64];                     // w_nin [n][c]
__device__ float  g_psum[NBLK * CB];
__device__ float  g_psq [NBLK * CB];
__device__ float  g_sc[2][CB];
__device__ float  g_sh[2][CB];

// ---------------- helpers ----------------
__device__ __forceinline__ uint32_t smem_u32(const void* p) {
    uint32_t a;
    asm("{ .reg .u64 t; cvta.to.shared.u64 t, %1; cvt.u32.u64 %0, t; }" : "=r"(a) : "l"(p));
    return a;
}
__device__ __forceinline__ void cpa16(uint32_t s, const void* g) {
    asm volatile("cp.async.cg.shared.global [%0], [%1], 16;" :: "r"(s), "l"(g));
}
__device__ __forceinline__ void cpa_commit() { asm volatile("cp.async.commit_group;" ::: "memory"); }
__device__ __forceinline__ void cpa_wait0()  { asm volatile("cp.async.wait_group 0;" ::: "memory"); }
__device__ __forceinline__ void ldsm4(uint32_t* d, uint32_t addr) {
    asm volatile("ldmatrix.sync.aligned.m8n8.x4.shared.b16 {%0,%1,%2,%3}, [%4];"
                 : "=r"(d[0]), "=r"(d[1]), "=r"(d[2]), "=r"(d[3]) : "r"(addr));
}
__device__ __forceinline__ void mma16(float* c, const uint32_t* a, const uint32_t* b) {
    asm volatile(
        "mma.sync.aligned.m16n8k16.row.col.f32.f16.f16.f32 "
        "{%0,%1,%2,%3}, {%4,%5,%6,%7}, {%8,%9}, {%0,%1,%2,%3};"
        : "+f"(c[0]), "+f"(c[1]), "+f"(c[2]), "+f"(c[3])
        : "r"(a[0]), "r"(a[1]), "r"(a[2]), "r"(a[3]), "r"(b[0]), "r"(b[1]));
}

// ---------------- BN stats: fp32 feats (+ zero p2t) ----------------
template <int C>
__global__ void k_bn_partial(const float* __restrict__ x) {
    const int tid = threadIdx.x;
    if (C == CA) {
        const int n4 = NPAD * 32 / 4;
        for (int i = blockIdx.x * 256 + tid; i < n4; i += NBLK * 256)
            ((int4*)g_p2t)[i] = make_int4(0, 0, 0, 0);
    }
    const int C4 = C / 4;
    float4 s = make_float4(0.f, 0.f, 0.f, 0.f);
    float4 q = make_float4(0.f, 0.f, 0.f, 0.f);
    const int tot = NV * C4;
    for (int i = blockIdx.x * 256 + tid; i < tot; i += NBLK * 256) {
        float4 v = ((const float4*)x)[i];
        s.x += v.x; s.y += v.y; s.z += v.z; s.w += v.w;
        q.x += v.x * v.x; q.y += v.y * v.y; q.z += v.z * v.z; q.w += v.w * v.w;
    }
    __shared__ float4 sh[256];
    sh[tid] = s;
    __syncthreads();
    if (tid < C4) {
        float4 a = sh[tid];
        for (int o = C4; o < 256; o += C4) {
            float4 b = sh[tid + o];
            a.x += b.x; a.y += b.y; a.z += b.z; a.w += b.w;
        }
        ((float4*)(g_psum + blockIdx.x * C))[tid] = a;
    }
    __syncthreads();
    sh[tid] = q;
    __syncthreads();
    if (tid < C4) {
        float4 a = sh[tid];
        for (int o = C4; o < 256; o += C4) {
            float4 b = sh[tid + o];
            a.x += b.x; a.y += b.y; a.z += b.z; a.w += b.w;
        }
        ((float4*)(g_psq + blockIdx.x * C))[tid] = a;
    }
}

// ---------------- BN stats: fp16 input (h1h), C = 128 ----------------
__global__ void k_bn_partial_h(const __half* __restrict__ x) {
    float s[8], q[8];
    #pragma unroll
    for (int t = 0; t < 8; ++t) { s[t] = 0.f; q[t] = 0.f; }
    const int tid = threadIdx.x;
    const int tot = NV * 16;
    for (int i = blockIdx.x * 256 + tid; i < tot; i += NBLK * 256) {
        uint4 v = ((const uint4*)x)[i];
        const uint32_t u[4] = {v.x, v.y, v.z, v.w};
        #pragma unroll
        for (int p = 0; p < 4; ++p) {
            float2 f = __half22float2(*(const __half2*)&u[p]);
            s[2 * p] += f.x; s[2 * p + 1] += f.y;
            q[2 * p] += f.x * f.x; q[2 * p + 1] += f.y * f.y;
        }
    }
    __shared__ float sh[256 * 8];
    #pragma unroll
    for (int t = 0; t < 8; ++t) sh[tid * 8 + t] = s[t];
    __syncthreads();
    if (tid < 128) {
        int cb = tid >> 3, ci = tid & 7;
        float a = 0.f;
        #pragma unroll
        for (int j = 0; j < 16; ++j) a += sh[(cb + 16 * j) * 8 + ci];
        g_psum[blockIdx.x * 128 + tid] = a;
    }
    __syncthreads();
    #pragma unroll
    for (int t = 0; t < 8; ++t) sh[tid * 8 + t] = q[t];
    __syncthreads();
    if (tid < 128) {
        int cb = tid >> 3, ci = tid & 7;
        float a = 0.f;
        #pragma unroll
        for (int j = 0; j < 16; ++j) a += sh[(cb + 16 * j) * 8 + ci];
        g_psq[blockIdx.x * 128 + tid] = a;
    }
}

template <int C, int IDX>
__global__ void k_bn_finalize(const float* __restrict__ gamma, const float* __restrict__ beta) {
    const int tid = threadIdx.x;   // blockDim = 4*C
    const int c = tid % C;
    const int qd = tid / C;
    float s = 0.f, s2 = 0.f;
    #pragma unroll 8
    for (int b = qd * (NBLK / 4); b < (qd + 1) * (NBLK / 4); ++b) {
        s  += g_psum[b * C + c];
        s2 += g_psq [b * C + c];
    }
    __shared__ float sha[4 * CB], shb[4 * CB];
    sha[tid] = s; shb[tid] = s2;
    __syncthreads();
    if (qd == 0) {
        s  = sha[c] + sha[C + c] + sha[2 * C + c] + sha[3 * C + c];
        s2 = shb[c] + shb[C + c] + shb[2 * C + c] + shb[3 * C + c];
        float mean = s / (float)NV;
        float var  = s2 / (float)NV - mean * mean;
        float a = rsqrtf(var + EPSF) * gamma[c];
        g_sc[IDX][c] = a;
        g_sh[IDX][c] = beta[c] - mean * a;
    }
}

// ---------------- prep1 ----------------
#define NB_F0  12500
#define NB_W1  864
#define NB_TBF 14
#define NB_MI  1
#define NB_MAP 21094
__global__ void k_prep1(const float* __restrict__ feats, const float* __restrict__ w1,
                        const int* __restrict__ sidx) {
    const int b = blockIdx.x;
    const int tid = threadIdx.x;
    if (b < NB_F0) {
        int i = b * 256 + tid;
        float4 v = ((const float4*)feats)[i];
        ((__half2*)g_f0h)[2 * i]     = __floats2half2_rn(v.x, v.y);
        ((__half2*)g_f0h)[2 * i + 1] = __floats2half2_rn(v.z, v.w);
    } else if (b < NB_F0 + NB_W1) {
        int i = (b - NB_F0) * 256 + tid;
        int k = i >> 13;
        int rem = i & 8191;
        int n = rem >> 6, c = rem & 63;
        g_w1h[i] = __float2half_rn(g_sc[0][c] * w1[(k * 64 + c) * 128 + n]);
    } else if (b < NB_F0 + NB_W1 + NB_TBF) {
        int i = (b - NB_F0 - NB_W1) * 256 + tid;
        if (i < KOFF * 128) {
            int k = i >> 7, n = i & 127;
            float acc = 0.f;
            for (int c = 0; c < 64; ++c)
                acc += g_sh[0][c] * w1[(k * 64 + c) * 128 + n];
            g_tb1f[i] = acc;
        }
    } else if (b < NB_F0 + NB_W1 + NB_TBF + NB_MI) {
        if (tid < 32)              ((__half2*)(g_f0h + NV * CA))[tid] = __half2half2(__ushort_as_half(0));
        if (tid >= 32 && tid < 96) ((__half2*)(g_h1h + NV * CB))[tid - 32] = __half2half2(__ushort_as_half(0));
    } else {
        int j = (b - NB_F0 - NB_W1 - NB_TBF - NB_MI) * 256 + tid;
        if (j < KOFF * NV) {
            int s = sidx[j];
            if (s < NV) {
                int k = j / NV;
                g_p2t[s * 32 + k] = (j - k * NV) + 1;
            }
        }
    }
}

// ---------------- prep2 ----------------
#define NB_W2  1728
#define NB_WN  32
__global__ void k_prep2(const float* __restrict__ w2, const float* __restrict__ wnin) {
    const int b = blockIdx.x;
    const int tid = threadIdx.x;
    if (b < NB_W2) {
        int i = b * 256 + tid;
        int k = i >> 14;
        int rem = i & 16383;
        int n = rem >> 7, c = rem & 127;
        g_w2h[i] = __float2half_rn(g_sc[1][c] * w2[(k * 128 + c) * 128 + n]);
    } else if (b < NB_W2 + NB_TBF) {
        int i = (b - NB_W2) * 256 + tid;
        if (i < KOFF * 128) {
            int k = i >> 7, n = i & 127;
            float acc = 0.f;
            for (int c = 0; c < 128; ++c)
                acc += g_sh[1][c] * w2[(k * 128 + c) * 128 + n];
            g_tb2f[i] = acc;
        }
    } else {
        int i = (b - NB_W2 - NB_TBF) * 256 + tid;
        int n = i >> 6, c = i & 63;
        g_wnh[i] = __float2half_rn(wnin[c * 128 + n]);
    }
}

// ---------------- compact per-k GEMM over valid slots ----------------
// grid = 27*TIL; CTA = (k, 128-slot tile); early-exit if tile fully padded.
// temp[(k*NPAD+slot)][n] = src[gidx[k,slot]] @ wfold[k] + tb[k][n]   (fp16)
template <int CIN>
__global__ void __launch_bounds__(256, 2)
k_convc(const __half* __restrict__ src, const __half* __restrict__ wt,
        const float* __restrict__ tbf, const int* __restrict__ gidx,
        const int* __restrict__ sidx, __half* __restrict__ temp) {
    const int kk   = blockIdx.x / TIL;
    const int tile = blockIdx.x - kk * TIL;
    if (sidx[kk * NV + tile * 128] >= NV) return;   // valid slots are prefix-compacted

    extern __shared__ __align__(16) char smraw[];
    constexpr int NCH = CIN / 64;
    float* sTB = (float*)(smraw + NCH * 32768);
    const uint32_t tile0 = smem_u32(smraw);

    const int tid  = threadIdx.x;
    const int lane = tid & 31;
    const int wid  = tid >> 5;
    const int g    = lane >> 2;
    const int tig  = lane & 3;
    const int warpRow = (wid & 3) * 32;
    const int warpCol = (wid >> 2) * 64;
    const int lr  = tid >> 3;
    const int sub = tid & 7;

    if (tid < 128) sTB[tid] = tbf[kk * 128 + tid];

    #pragma unroll
    for (int c = 0; c < NCH; ++c) {
        const uint32_t aB = tile0 + (uint32_t)c * 32768u;
        const uint32_t bB = aB + 16384u;
        #pragma unroll
        for (int j = 0; j < 4; ++j) {
            int r = lr + j * 32;
            int slot = tile * 128 + r;
            int gg = (slot < NV) ? gidx[kk * NV + slot] : NV;
            uint32_t off = (uint32_t)((r << 7) + ((sub ^ (r & 7)) << 4));
            cpa16(aB + off, src + (size_t)gg * CIN + c * 64 + sub * 8);
        }
        const __half* bs = wt + ((size_t)kk * 128) * CIN + c * 64;
        #pragma unroll
        for (int j = 0; j < 4; ++j) {
            int n = lr + j * 32;
            uint32_t off = (uint32_t)((n << 7) + ((sub ^ (n & 7)) << 4));
            cpa16(bB + off, bs + (size_t)n * CIN + sub * 8);
        }
    }
    cpa_commit();
    cpa_wait0();
    __syncthreads();

    float acc[2][8][4];
    #pragma unroll
    for (int mt = 0; mt < 2; ++mt)
        #pragma unroll
        for (int nt = 0; nt < 8; ++nt)
            #pragma unroll
            for (int q = 0; q < 4; ++q) acc[mt][nt][q] = 0.f;

    const int s7 = lane & 7;
    const int rowA = warpRow + s7 + ((lane >> 3) & 1) * 8;
    const int uA   = lane >> 4;
    const int rowB = warpCol + s7 + (lane >> 4) * 8;
    const int uB   = (lane >> 3) & 1;

    #pragma unroll
    for (int c = 0; c < NCH; ++c) {
        const uint32_t aB = tile0 + (uint32_t)c * 32768u;
        const uint32_t bB = aB + 16384u;
        const uint32_t pa0 = aB + ((uint32_t)rowA << 7);
        const uint32_t pa1 = aB + ((uint32_t)(rowA + 16) << 7);
        #pragma unroll
        for (int ks = 0; ks < 4; ++ks) {
            const int u0 = ks * 2;
            uint32_t a[2][4];
            const uint32_t aoff = (uint32_t)(((u0 + uA) ^ s7) << 4);
            ldsm4(a[0], pa0 + aoff);
            ldsm4(a[1], pa1 + aoff);
            const uint32_t boff = (uint32_t)(((u0 + uB) ^ s7) << 4);
            #pragma unroll
            for (int p = 0; p < 4; ++p) {
                uint32_t bfr[4];
                ldsm4(bfr, bB + ((uint32_t)(rowB + p * 16) << 7) + boff);
                mma16(acc[0][2 * p],     a[0], &bfr[0]);
                mma16(acc[0][2 * p + 1], a[0], &bfr[2]);
                mma16(acc[1][2 * p],     a[1], &bfr[0]);
                mma16(acc[1][2 * p + 1], a[1], &bfr[2]);
            }
        }
    }

    #pragma unroll
    for (int mt = 0; mt < 2; ++mt) {
        int slot0 = tile * 128 + warpRow + mt * 16 + g;
        #pragma unroll
        for (int nt = 0; nt < 8; ++nt) {
            int col = warpCol + nt * 8 + 2 * tig;
            float t0 = sTB[col], t1 = sTB[col + 1];
            __half2 v0 = __floats2half2_rn(acc[mt][nt][0] + t0, acc[mt][nt][1] + t1);
            __half2 v1 = __floats2half2_rn(acc[mt][nt][2] + t0, acc[mt][nt][3] + t1);
            *(__half2*)(temp + ((size_t)kk * NPAD + slot0) * 128 + col)     = v0;
            *(__half2*)(temp + ((size_t)kk * NPAD + slot0 + 8) * 128 + col) = v1;
        }
    }
}

// ---------------- dense skip GEMM: base2 = f0h @ w_nin (fp32) ----------------
__global__ void __launch_bounds__(256, 2)
k_base2(const __half* __restrict__ src, const __half* __restrict__ wnh,
        float* __restrict__ base2) {
    extern __shared__ __align__(16) char smraw[];
    const uint32_t tile0 = smem_u32(smraw);
    const int tid  = threadIdx.x;
    const int lane = tid & 31;
    const int wid  = tid >> 5;
    const int g    = lane >> 2;
    const int tig  = lane & 3;
    const int tile = blockIdx.x;
    const int warpRow = (wid & 3) * 32;
    const int warpCol = (wid >> 2) * 64;
    const int lr  = tid >> 3;
    const int sub = tid & 7;

    const uint32_t aB = tile0, bB = tile0 + 16384u;
    #pragma unroll
    for (int j = 0; j < 4; ++j) {
        int r = lr + j * 32;
        int row = tile * 128 + r;
        int gg = (row < NV) ? row : NV;
        uint32_t off = (uint32_t)((r << 7) + ((sub ^ (r & 7)) << 4));
        cpa16(aB + off, src + (size_t)gg * 64 + sub * 8);
    }
    #pragma unroll
    for (int j = 0; j < 4; ++j) {
        int n = lr + j * 32;
        uint32_t off = (uint32_t)((n << 7) + ((sub ^ (n & 7)) << 4));
        cpa16(bB + off, wnh + (size_t)n * 64 + sub * 8);
    }
    cpa_commit();
    cpa_wait0();
    __syncthreads();

    float acc[2][8][4];
    #pragma unroll
    for (int mt = 0; mt < 2; ++mt)
        #pragma unroll
        for (int nt = 0; nt < 8; ++nt)
            #pragma unroll
            for (int q = 0; q < 4; ++q) acc[mt][nt][q] = 0.f;

    const int s7 = lane & 7;
    const int rowA = warpRow + s7 + ((lane >> 3) & 1) * 8;
    const int uA   = lane >> 4;
    const int rowB = warpCol + s7 + (lane >> 4) * 8;
    const int uB   = (lane >> 3) & 1;
    const uint32_t pa0 = aB + ((uint32_t)rowA << 7);
    const uint32_t pa1 = aB + ((uint32_t)(rowA + 16) << 7);

    #pragma unroll
    for (int ks = 0; ks < 4; ++ks) {
        const int u0 = ks * 2;
        uint32_t a[2][4];
        const uint32_t aoff = (uint32_t)(((u0 + uA) ^ s7) << 4);
        ldsm4(a[0], pa0 + aoff);
        ldsm4(a[1], pa1 + aoff);
        const uint32_t boff = (uint32_t)(((u0 + uB) ^ s7) << 4);
        #pragma unroll
        for (int p = 0; p < 4; ++p) {
            uint32_t bfr[4];
            ldsm4(bfr, bB + ((uint32_t)(rowB + p * 16) << 7) + boff);
            mma16(acc[0][2 * p],     a[0], &bfr[0]);
            mma16(acc[0][2 * p + 1], a[0], &bfr[2]);
            mma16(acc[1][2 * p],     a[1], &bfr[0]);
            mma16(acc[1][2 * p + 1], a[1], &bfr[2]);
        }
    }

    #pragma unroll
    for (int mt = 0; mt < 2; ++mt) {
        int r0 = tile * 128 + warpRow + mt * 16 + g;
        #pragma unroll
        for (int nt = 0; nt < 8; ++nt) {
            int col = warpCol + nt * 8 + 2 * tig;
            *(float2*)(base2 + (size_t)r0 * 128 + col) =
                make_float2(acc[mt][nt][0], acc[mt][nt][1]);
            *(float2*)(base2 + (size_t)(r0 + 8) * 128 + col) =
                make_float2(acc[mt][nt][2], acc[mt][nt][3]);
        }
    }
}

// ---------------- gather-reduce: out[i] = (base[i]) + sum_k temp[k, slot(k,i)] ----
// 256 thr = 8 rows/block; warp per row; lane owns 4 cols. grid = NV/8 = 25000.
template <bool FINAL>
__global__ void __launch_bounds__(256)
k_reduce(const __half* __restrict__ temp, const float* __restrict__ base,
         void* __restrict__ dstv) {
    const int lane = threadIdx.x & 31;
    const int w    = threadIdx.x >> 5;
    const int i    = blockIdx.x * 8 + w;

    int myp = g_p2t[i * 32 + lane];   // lanes 27-31 read zeros
    float a0, a1, a2, a3;
    if (FINAL) {
        float4 b = ((const float4*)(base + (size_t)i * 128))[lane];
        a0 = b.x; a1 = b.y; a2 = b.z; a3 = b.w;
    } else {
        a0 = a1 = a2 = a3 = 0.f;
    }
    #pragma unroll
    for (int k = 0; k < KOFF; ++k) {
        int sp = __shfl_sync(0xffffffffu, myp, k);
        if (sp) {
            const __half2* p = (const __half2*)(temp + ((size_t)k * NPAD + (sp - 1)) * 128) + lane * 2;
            float2 x = __half22float2(p[0]);
            float2 y = __half22float2(p[1]);
            a0 += x.x; a1 += x.y; a2 += y.x; a3 += y.y;
        }
    }
    if (FINAL) {
        ((float4*)dstv)[(size_t)i * 32 + lane] = make_float4(a0, a1, a2, a3);
    } else {
        __half2* o = (__half2*)((__half*)dstv + (size_t)i * 128) + lane * 2;
        o[0] = __floats2half2_rn(a0, a1);
        o[1] = __floats2half2_rn(a2, a3);
    }
}

// ---------------- launch ----------------
extern "C" void kernel_launch(void* const* d_in, const int* in_sizes, int n_in,
                              void* d_out, int out_size) {
    const float* feats     = (const float*)d_in[0];
    const float* w1        = (const float*)d_in[1];
    const float* w2        = (const float*)d_in[2];
    const float* w_nin     = (const float*)d_in[3];
    const float* bn1_gamma = (const float*)d_in[4];
    const float* bn1_beta  = (const float*)d_in[5];
    const float* bn2_gamma = (const float*)d_in[6];
    const float* bn2_beta  = (const float*)d_in[7];
    const int*   gidx      = (const int*)d_in[8];
    const int*   sidx      = (const int*)d_in[9];
    float*       out       = (float*)d_out;

    const int sm1 = 1 * 32768 + 512;    // k_convc<64>  : A+B + tb row
    const int sm2 = 2 * 32768 + 512;    // k_convc<128>
    const int smb = 32768;              // k_base2
    cudaFuncSetAttribute(k_convc<CA>, cudaFuncAttributeMaxDynamicSharedMemorySize, sm1);
    cudaFuncSetAttribute(k_convc<CB>, cudaFuncAttributeMaxDynamicSharedMemorySize, sm2);
    cudaFuncSetAttribute(k_base2,     cudaFuncAttributeMaxDynamicSharedMemorySize, smb);

    __half *f0h, *h1h, *w1h, *w2h, *wnh, *temp;
    float  *tb1f, *tb2f, *base2;
    cudaGetSymbolAddress((void**)&f0h,  g_f0h);
    cudaGetSymbolAddress((void**)&h1h,  g_h1h);
    cudaGetSymbolAddress((void**)&w1h,  g_w1h);
    cudaGetSymbolAddress((void**)&w2h,  g_w2h);
    cudaGetSymbolAddress((void**)&wnh,  g_wnh);
    cudaGetSymbolAddress((void**)&temp, g_temp);
    cudaGetSymbolAddress((void**)&tb1f, g_tb1f);
    cudaGetSymbolAddress((void**)&tb2f, g_tb2f);
    cudaGetSymbolAddress((void**)&base2, g_base2);

    // 1-2: BN1 stats (+ p2t zero)
    k_bn_partial<CA><<<NBLK, 256>>>(feats);
    k_bn_finalize<CA, 0><<<1, 4 * CA>>>(bn1_gamma, bn1_beta);
    // 3: prep (f0h, fold w1, tb1, dummy rows, p2t scatter)
    k_prep1<<<NB_F0 + NB_W1 + NB_TBF + NB_MI + NB_MAP, 256>>>(feats, w1, sidx);
    // 4: conv1 compact GEMM (profiled slot)
    k_convc<CA><<<KOFF * TIL, 256, sm1>>>(f0h, w1h, tb1f, gidx, sidx, temp);
    // 5: reduce -> h1h (raw conv1, fp16)
    k_reduce<false><<<NV / 8, 256>>>(temp, nullptr, h1h);
    // 6-7: BN2 stats
    k_bn_partial_h<<<NBLK, 256>>>(h1h);
    k_bn_finalize<CB, 1><<<1, 4 * CB>>>(bn2_gamma, bn2_beta);
    // 8: prep2 (fold w2, tb2, wnh)
    k_prep2<<<NB_W2 + NB_TBF + NB_WN, 256>>>(w2, w_nin);
    // 9: skip GEMM
    k_base2<<<TIL, 256, smb>>>(f0h, wnh, base2);
    // 10: conv2 compact GEMM
    k_convc<CB><<<KOFF * TIL, 256, sm2>>>(h1h, w2h, tb2f, gidx, sidx, temp);
    // 11: final reduce -> out (fp32)
    k_reduce<true><<<NV / 8, 256>>>(temp, base2, out);
}

// round 13
// speedup vs baseline: 1.7573x; 1.0964x over previous
#include <cuda_runtime.h>
#include <cuda_fp16.h>
#include <cstdint>

#define NV   200000
#define NPAD 200064
#define TIL  1563
#define KOFF 27
#define CA   64
#define CB   128
#define NBLK 256
#define EPSF 1e-5f

// ---------------- device scratch ----------------
__device__ __half g_f0h[(NV + 1) * CA];
__device__ __half g_h1h[(NV + 1) * CB];
__device__ __half g_temp[(size_t)KOFF * NPAD * 128];  // fp16 partial rows, 1.38 GB
__device__ int    g_p2t[NPAD * 32];                   // per-output slot+1 per k (0=invalid)
__device__ __half g_base2h[(size_t)NPAD * 128];       // skip GEMM out (fp16)
__device__ __half g_w1h[KOFF * CB * CA];              // bn1-folded w1 [k][n][c]
__device__ __half g_w2h[KOFF * CB * CB];              // bn2-folded w2 [k][n][c]
__device__ float  g_tb1f[KOFF * 128];                 // bias row per (k,n)
__device__ float  g_tb2f[KOFF * 128];
__device__ __half g_wnh[CB * 64];                     // w_nin [n][c]
__device__ float  g_psum[NBLK * CB];
__device__ float  g_psq [NBLK * CB];
__device__ float  g_sc[2][CB];
__device__ float  g_sh[2][CB];

// ---------------- helpers ----------------
__device__ __forceinline__ uint32_t smem_u32(const void* p) {
    uint32_t a;
    asm("{ .reg .u64 t; cvta.to.shared.u64 t, %1; cvt.u32.u64 %0, t; }" : "=r"(a) : "l"(p));
    return a;
}
__device__ __forceinline__ void cpa16(uint32_t s, const void* g) {
    asm volatile("cp.async.cg.shared.global [%0], [%1], 16;" :: "r"(s), "l"(g));
}
__device__ __forceinline__ void cpa_commit() { asm volatile("cp.async.commit_group;" ::: "memory"); }
__device__ __forceinline__ void cpa_wait1()  { asm volatile("cp.async.wait_group 1;" ::: "memory"); }
__device__ __forceinline__ void cpa_wait0()  { asm volatile("cp.async.wait_group 0;" ::: "memory"); }
__device__ __forceinline__ void ldsm4(uint32_t* d, uint32_t addr) {
    asm volatile("ldmatrix.sync.aligned.m8n8.x4.shared.b16 {%0,%1,%2,%3}, [%4];"
                 : "=r"(d[0]), "=r"(d[1]), "=r"(d[2]), "=r"(d[3]) : "r"(addr));
}
__device__ __forceinline__ void mma16(float* c, const uint32_t* a, const uint32_t* b) {
    asm volatile(
        "mma.sync.aligned.m16n8k16.row.col.f32.f16.f16.f32 "
        "{%0,%1,%2,%3}, {%4,%5,%6,%7}, {%8,%9}, {%0,%1,%2,%3};"
        : "+f"(c[0]), "+f"(c[1]), "+f"(c[2]), "+f"(c[3])
        : "r"(a[0]), "r"(a[1]), "r"(a[2]), "r"(a[3]), "r"(b[0]), "r"(b[1]));
}
__device__ __forceinline__ void stcs32(void* p, uint32_t v) {
    asm volatile("st.global.cs.b32 [%0], %1;" :: "l"(p), "r"(v) : "memory");
}
__device__ __forceinline__ uint2 ldcs64(const void* p) {
    uint2 r;
    asm volatile("ld.global.cs.v2.b32 {%0,%1}, [%2];" : "=r"(r.x), "=r"(r.y) : "l"(p));
    return r;
}

// ---------------- BN stats: fp32 feats (+ zero p2t) ----------------
template <int C>
__global__ void k_bn_partial(const float* __restrict__ x) {
    const int tid = threadIdx.x;
    if (C == CA) {
        const int n4 = NPAD * 32 / 4;
        for (int i = blockIdx.x * 256 + tid; i < n4; i += NBLK * 256)
            ((int4*)g_p2t)[i] = make_int4(0, 0, 0, 0);
    }
    const int C4 = C / 4;
    float4 s = make_float4(0.f, 0.f, 0.f, 0.f);
    float4 q = make_float4(0.f, 0.f, 0.f, 0.f);
    const int tot = NV * C4;
    for (int i = blockIdx.x * 256 + tid; i < tot; i += NBLK * 256) {
        float4 v = ((const float4*)x)[i];
        s.x += v.x; s.y += v.y; s.z += v.z; s.w += v.w;
        q.x += v.x * v.x; q.y += v.y * v.y; q.z += v.z * v.z; q.w += v.w * v.w;
    }
    __shared__ float4 sh[256];
    sh[tid] = s;
    __syncthreads();
    if (tid < C4) {
        float4 a = sh[tid];
        for (int o = C4; o < 256; o += C4) {
            float4 b = sh[tid + o];
            a.x += b.x; a.y += b.y; a.z += b.z; a.w += b.w;
        }
        ((float4*)(g_psum + blockIdx.x * C))[tid] = a;
    }
    __syncthreads();
    sh[tid] = q;
    __syncthreads();
    if (tid < C4) {
        float4 a = sh[tid];
        for (int o = C4; o < 256; o += C4) {
            float4 b = sh[tid + o];
            a.x += b.x; a.y += b.y; a.z += b.z; a.w += b.w;
        }
        ((float4*)(g_psq + blockIdx.x * C))[tid] = a;
    }
}

// ---------------- BN stats: fp16 input (h1h), C = 128 ----------------
__global__ void k_bn_partial_h(const __half* __restrict__ x) {
    float s[8], q[8];
    #pragma unroll
    for (int t = 0; t < 8; ++t) { s[t] = 0.f; q[t] = 0.f; }
    const int tid = threadIdx.x;
    const int tot = NV * 16;
    for (int i = blockIdx.x * 256 + tid; i < tot; i += NBLK * 256) {
        uint4 v = ((const uint4*)x)[i];
        const uint32_t u[4] = {v.x, v.y, v.z, v.w};
        #pragma unroll
        for (int p = 0; p < 4; ++p) {
            float2 f = __half22float2(*(const __half2*)&u[p]);
            s[2 * p] += f.x; s[2 * p + 1] += f.y;
            q[2 * p] += f.x * f.x; q[2 * p + 1] += f.y * f.y;
        }
    }
    __shared__ float sh[256 * 8];
    #pragma unroll
    for (int t = 0; t < 8; ++t) sh[tid * 8 + t] = s[t];
    __syncthreads();
    if (tid < 128) {
        int cb = tid >> 3, ci = tid & 7;
        float a = 0.f;
        #pragma unroll
        for (int j = 0; j < 16; ++j) a += sh[(cb + 16 * j) * 8 + ci];
        g_psum[blockIdx.x * 128 + tid] = a;
    }
    __syncthreads();
    #pragma unroll
    for (int t = 0; t < 8; ++t) sh[tid * 8 + t] = q[t];
    __syncthreads();
    if (tid < 128) {
        int cb = tid >> 3, ci = tid & 7;
        float a = 0.f;
        #pragma unroll
        for (int j = 0; j < 16; ++j) a += sh[(cb + 16 * j) * 8 + ci];
        g_psq[blockIdx.x * 128 + tid] = a;
    }
}

template <int C, int IDX>
__global__ void k_bn_finalize(const float* __restrict__ gamma, const float* __restrict__ beta) {
    const int tid = threadIdx.x;   // blockDim = 4*C
    const int c = tid % C;
    const int qd = tid / C;
    float s = 0.f, s2 = 0.f;
    #pragma unroll 8
    for (int b = qd * (NBLK / 4); b < (qd + 1) * (NBLK / 4); ++b) {
        s  += g_psum[b * C + c];
        s2 += g_psq [b * C + c];
    }
    __shared__ float sha[4 * CB], shb[4 * CB];
    sha[tid] = s; shb[tid] = s2;
    __syncthreads();
    if (qd == 0) {
        s  = sha[c] + sha[C + c] + sha[2 * C + c] + sha[3 * C + c];
        s2 = shb[c] + shb[C + c] + shb[2 * C + c] + shb[3 * C + c];
        float mean = s / (float)NV;
        float var  = s2 / (float)NV - mean * mean;
        float a = rsqrtf(var + EPSF) * gamma[c];
        g_sc[IDX][c] = a;
        g_sh[IDX][c] = beta[c] - mean * a;
    }
}

// ---------------- prep1 ----------------
#define NB_F0  12500
#define NB_W1  864
#define NB_TBF 14
#define NB_MI  1
#define NB_MAP 21094
__global__ void k_prep1(const float* __restrict__ feats, const float* __restrict__ w1,
                        const int* __restrict__ sidx) {
    const int b = blockIdx.x;
    const int tid = threadIdx.x;
    if (b < NB_F0) {
        int i = b * 256 + tid;
        float4 v = ((const float4*)feats)[i];
        ((__half2*)g_f0h)[2 * i]     = __floats2half2_rn(v.x, v.y);
        ((__half2*)g_f0h)[2 * i + 1] = __floats2half2_rn(v.z, v.w);
    } else if (b < NB_F0 + NB_W1) {
        int i = (b - NB_F0) * 256 + tid;
        int k = i >> 13;
        int rem = i & 8191;
        int n = rem >> 6, c = rem & 63;
        g_w1h[i] = __float2half_rn(g_sc[0][c] * w1[(k * 64 + c) * 128 + n]);
    } else if (b < NB_F0 + NB_W1 + NB_TBF) {
        int i = (b - NB_F0 - NB_W1) * 256 + tid;
        if (i < KOFF * 128) {
            int k = i >> 7, n = i & 127;
            float acc = 0.f;
            for (int c = 0; c < 64; ++c)
                acc += g_sh[0][c] * w1[(k * 64 + c) * 128 + n];
            g_tb1f[i] = acc;
        }
    } else if (b < NB_F0 + NB_W1 + NB_TBF + NB_MI) {
        if (tid < 32)              ((__half2*)(g_f0h + NV * CA))[tid] = __half2half2(__ushort_as_half(0));
        if (tid >= 32 && tid < 96) ((__half2*)(g_h1h + NV * CB))[tid - 32] = __half2half2(__ushort_as_half(0));
    } else {
        int j = (b - NB_F0 - NB_W1 - NB_TBF - NB_MI) * 256 + tid;
        if (j < KOFF * NV) {
            int s = sidx[j];
            if (s < NV) {
                int k = j / NV;
                g_p2t[s * 32 + k] = (j - k * NV) + 1;
            }
        }
    }
}

// ---------------- prep2 ----------------
#define NB_W2  1728
#define NB_WN  32
__global__ void k_prep2(const float* __restrict__ w2, const float* __restrict__ wnin) {
    const int b = blockIdx.x;
    const int tid = threadIdx.x;
    if (b < NB_W2) {
        int i = b * 256 + tid;
        int k = i >> 14;
        int rem = i & 16383;
        int n = rem >> 7, c = rem & 127;
        g_w2h[i] = __float2half_rn(g_sc[1][c] * w2[(k * 128 + c) * 128 + n]);
    } else if (b < NB_W2 + NB_TBF) {
        int i = (b - NB_W2) * 256 + tid;
        if (i < KOFF * 128) {
            int k = i >> 7, n = i & 127;
            float acc = 0.f;
            for (int c = 0; c < 128; ++c)
                acc += g_sh[1][c] * w2[(k * 128 + c) * 128 + n];
            g_tb2f[i] = acc;
        }
    } else {
        int i = (b - NB_W2 - NB_TBF) * 256 + tid;
        int n = i >> 6, c = i & 63;
        g_wnh[i] = __float2half_rn(wnin[c * 128 + n]);
    }
}

// ---------------- compact per-k GEMM over valid slots ----------------
// grid = 27*TIL; CTA = (k, 128-slot tile); early-exit if tile fully padded.
// temp[(k*NPAD+slot)][n] = src[gidx[k,slot]] @ wfold[k] + tb[k][n]   (fp16, .cs)
template <int CIN>
__global__ void __launch_bounds__(256, 2)
k_convc(const __half* __restrict__ src, const __half* __restrict__ wt,
        const float* __restrict__ tbf, const int* __restrict__ gidx,
        const int* __restrict__ sidx, __half* __restrict__ temp) {
    const int kk   = blockIdx.x / TIL;
    const int tile = blockIdx.x - kk * TIL;
    if (sidx[kk * NV + tile * 128] >= NV) return;   // valid slots are prefix-compacted

    extern __shared__ __align__(16) char smraw[];
    constexpr int NCH = CIN / 64;
    float* sTB = (float*)(smraw + NCH * 32768);
    const uint32_t tile0 = smem_u32(smraw);

    const int tid  = threadIdx.x;
    const int lane = tid & 31;
    const int wid  = tid >> 5;
    const int g    = lane >> 2;
    const int tig  = lane & 3;
    const int warpRow = (wid & 3) * 32;
    const int warpCol = (wid >> 2) * 64;
    const int lr  = tid >> 3;
    const int sub = tid & 7;

    if (tid < 128) sTB[tid] = tbf[kk * 128 + tid];

    // issue loads per chunk (separate commit groups for pipelining)
    #pragma unroll
    for (int c = 0; c < NCH; ++c) {
        const uint32_t aB = tile0 + (uint32_t)c * 32768u;
        const uint32_t bB = aB + 16384u;
        #pragma unroll
        for (int j = 0; j < 4; ++j) {
            int r = lr + j * 32;
            int slot = tile * 128 + r;
            int gg = (slot < NV) ? gidx[kk * NV + slot] : NV;
            uint32_t off = (uint32_t)((r << 7) + ((sub ^ (r & 7)) << 4));
            cpa16(aB + off, src + (size_t)gg * CIN + c * 64 + sub * 8);
        }
        const __half* bs = wt + ((size_t)kk * 128) * CIN + c * 64;
        #pragma unroll
        for (int j = 0; j < 4; ++j) {
            int n = lr + j * 32;
            uint32_t off = (uint32_t)((n << 7) + ((sub ^ (n & 7)) << 4));
            cpa16(bB + off, bs + (size_t)n * CIN + sub * 8);
        }
        cpa_commit();
    }

    float acc[2][8][4];
    #pragma unroll
    for (int mt = 0; mt < 2; ++mt)
        #pragma unroll
        for (int nt = 0; nt < 8; ++nt)
            #pragma unroll
            for (int q = 0; q < 4; ++q) acc[mt][nt][q] = 0.f;

    const int s7 = lane & 7;
    const int rowA = warpRow + s7 + ((lane >> 3) & 1) * 8;
    const int uA   = lane >> 4;
    const int rowB = warpCol + s7 + (lane >> 4) * 8;
    const int uB   = (lane >> 3) & 1;

    #pragma unroll
    for (int c = 0; c < NCH; ++c) {
        if (NCH == 2 && c == 0) cpa_wait1(); else cpa_wait0();
        __syncthreads();
        const uint32_t aB = tile0 + (uint32_t)c * 32768u;
        const uint32_t bB = aB + 16384u;
        const uint32_t pa0 = aB + ((uint32_t)rowA << 7);
        const uint32_t pa1 = aB + ((uint32_t)(rowA + 16) << 7);
        #pragma unroll
        for (int ks = 0; ks < 4; ++ks) {
            const int u0 = ks * 2;
            uint32_t a[2][4];
            const uint32_t aoff = (uint32_t)(((u0 + uA) ^ s7) << 4);
            ldsm4(a[0], pa0 + aoff);
            ldsm4(a[1], pa1 + aoff);
            const uint32_t boff = (uint32_t)(((u0 + uB) ^ s7) << 4);
            #pragma unroll
            for (int p = 0; p < 4; ++p) {
                uint32_t bfr[4];
                ldsm4(bfr, bB + ((uint32_t)(rowB + p * 16) << 7) + boff);
                mma16(acc[0][2 * p],     a[0], &bfr[0]);
                mma16(acc[0][2 * p + 1], a[0], &bfr[2]);
                mma16(acc[1][2 * p],     a[1], &bfr[0]);
                mma16(acc[1][2 * p + 1], a[1], &bfr[2]);
            }
        }
    }

    #pragma unroll
    for (int mt = 0; mt < 2; ++mt) {
        int slot0 = tile * 128 + warpRow + mt * 16 + g;
        #pragma unroll
        for (int nt = 0; nt < 8; ++nt) {
            int col = warpCol + nt * 8 + 2 * tig;
            float t0 = sTB[col], t1 = sTB[col + 1];
            __half2 v0 = __floats2half2_rn(acc[mt][nt][0] + t0, acc[mt][nt][1] + t1);
            __half2 v1 = __floats2half2_rn(acc[mt][nt][2] + t0, acc[mt][nt][3] + t1);
            stcs32(temp + ((size_t)kk * NPAD + slot0) * 128 + col,     *(uint32_t*)&v0);
            stcs32(temp + ((size_t)kk * NPAD + slot0 + 8) * 128 + col, *(uint32_t*)&v1);
        }
    }
}

// ---------------- dense skip GEMM: base2h = f0h @ w_nin (fp16) ----------------
__global__ void __launch_bounds__(256, 2)
k_base2(const __half* __restrict__ src, const __half* __restrict__ wnh,
        __half* __restrict__ baseh) {
    extern __shared__ __align__(16) char smraw[];
    const uint32_t tile0 = smem_u32(smraw);
    const int tid  = threadIdx.x;
    const int lane = tid & 31;
    const int wid  = tid >> 5;
    const int g    = lane >> 2;
    const int tig  = lane & 3;
    const int tile = blockIdx.x;
    const int warpRow = (wid & 3) * 32;
    const int warpCol = (wid >> 2) * 64;
    const int lr  = tid >> 3;
    const int sub = tid & 7;

    const uint32_t aB = tile0, bB = tile0 + 16384u;
    #pragma unroll
    for (int j = 0; j < 4; ++j) {
        int r = lr + j * 32;
        int row = tile * 128 + r;
        int gg = (row < NV) ? row : NV;
        uint32_t off = (uint32_t)((r << 7) + ((sub ^ (r & 7)) << 4));
        cpa16(aB + off, src + (size_t)gg * 64 + sub * 8);
    }
    #pragma unroll
    for (int j = 0; j < 4; ++j) {
        int n = lr + j * 32;
        uint32_t off = (uint32_t)((n << 7) + ((sub ^ (n & 7)) << 4));
        cpa16(bB + off, wnh + (size_t)n * 64 + sub * 8);
    }
    cpa_commit();
    cpa_wait0();
    __syncthreads();

    float acc[2][8][4];
    #pragma unroll
    for (int mt = 0; mt < 2; ++mt)
        #pragma unroll
        for (int nt = 0; nt < 8; ++nt)
            #pragma unroll
            for (int q = 0; q < 4; ++q) acc[mt][nt][q] = 0.f;

    const int s7 = lane & 7;
    const int rowA = warpRow + s7 + ((lane >> 3) & 1) * 8;
    const int uA   = lane >> 4;
    const int rowB = warpCol + s7 + (lane >> 4) * 8;
    const int uB   = (lane >> 3) & 1;
    const uint32_t pa0 = aB + ((uint32_t)rowA << 7);
    const uint32_t pa1 = aB + ((uint32_t)(rowA + 16) << 7);

    #pragma unroll
    for (int ks = 0; ks < 4; ++ks) {
        const int u0 = ks * 2;
        uint32_t a[2][4];
        const uint32_t aoff = (uint32_t)(((u0 + uA) ^ s7) << 4);
        ldsm4(a[0], pa0 + aoff);
        ldsm4(a[1], pa1 + aoff);
        const uint32_t boff = (uint32_t)(((u0 + uB) ^ s7) << 4);
        #pragma unroll
        for (int p = 0; p < 4; ++p) {
            uint32_t bfr[4];
            ldsm4(bfr, bB + ((uint32_t)(rowB + p * 16) << 7) + boff);
            mma16(acc[0][2 * p],     a[0], &bfr[0]);
            mma16(acc[0][2 * p + 1], a[0], &bfr[2]);
            mma16(acc[1][2 * p],     a[1], &bfr[0]);
            mma16(acc[1][2 * p + 1], a[1], &bfr[2]);
        }
    }

    #pragma unroll
    for (int mt = 0; mt < 2; ++mt) {
        int r0 = tile * 128 + warpRow + mt * 16 + g;
        #pragma unroll
        for (int nt = 0; nt < 8; ++nt) {
            int col = warpCol + nt * 8 + 2 * tig;
            __half2 v0 = __floats2half2_rn(acc[mt][nt][0], acc[mt][nt][1]);
            __half2 v1 = __floats2half2_rn(acc[mt][nt][2], acc[mt][nt][3]);
            *(__half2*)(baseh + (size_t)r0 * 128 + col)       = v0;
            *(__half2*)(baseh + (size_t)(r0 + 8) * 128 + col) = v1;
        }
    }
}

// ---------------- gather-reduce: out[i] = (base[i]) + sum_k temp[k, slot(k,i)] ----
// warp per output row; lane owns 4 cols. grid = NV/8.
template <bool FINAL>
__global__ void __launch_bounds__(256)
k_reduce(const __half* __restrict__ temp, const __half* __restrict__ baseh,
         void* __restrict__ dstv) {
    const int lane = threadIdx.x & 31;
    const int w    = threadIdx.x >> 5;
    const int i    = blockIdx.x * 8 + w;

    int myp = g_p2t[i * 32 + lane];   // lanes 27-31 read zeros
    float a0, a1, a2, a3;
    if (FINAL) {
        uint2 b = ldcs64(baseh + (size_t)i * 128 + lane * 4);
        float2 b0 = __half22float2(*(__half2*)&b.x);
        float2 b1 = __half22float2(*(__half2*)&b.y);
        a0 = b0.x; a1 = b0.y; a2 = b1.x; a3 = b1.y;
    } else {
        a0 = a1 = a2 = a3 = 0.f;
    }
    #pragma unroll
    for (int k = 0; k < KOFF; ++k) {
        int sp = __shfl_sync(0xffffffffu, myp, k);
        if (sp) {
            uint2 v = ldcs64(temp + ((size_t)k * NPAD + (sp - 1)) * 128 + lane * 4);
            float2 x = __half22float2(*(__half2*)&v.x);
            float2 y = __half22float2(*(__half2*)&v.y);
            a0 += x.x; a1 += x.y; a2 += y.x; a3 += y.y;
        }
    }
    if (FINAL) {
        ((float4*)dstv)[(size_t)i * 32 + lane] = make_float4(a0, a1, a2, a3);
    } else {
        __half2* o = (__half2*)((__half*)dstv + (size_t)i * 128) + lane * 2;
        o[0] = __floats2half2_rn(a0, a1);
        o[1] = __floats2half2_rn(a2, a3);
    }
}

// ---------------- launch ----------------
extern "C" void kernel_launch(void* const* d_in, const int* in_sizes, int n_in,
                              void* d_out, int out_size) {
    const float* feats     = (const float*)d_in[0];
    const float* w1        = (const float*)d_in[1];
    const float* w2        = (const float*)d_in[2];
    const float* w_nin     = (const float*)d_in[3];
    const float* bn1_gamma = (const float*)d_in[4];
    const float* bn1_beta  = (const float*)d_in[5];
    const float* bn2_gamma = (const float*)d_in[6];
    const float* bn2_beta  = (const float*)d_in[7];
    const int*   gidx      = (const int*)d_in[8];
    const int*   sidx      = (const int*)d_in[9];
    float*       out       = (float*)d_out;

    const int sm1 = 1 * 32768 + 512;
    const int sm2 = 2 * 32768 + 512;
    const int smb = 32768;
    cudaFuncSetAttribute(k_convc<CA>, cudaFuncAttributeMaxDynamicSharedMemorySize, sm1);
    cudaFuncSetAttribute(k_convc<CB>, cudaFuncAttributeMaxDynamicSharedMemorySize, sm2);
    cudaFuncSetAttribute(k_base2,     cudaFuncAttributeMaxDynamicSharedMemorySize, smb);

    __half *f0h, *h1h, *w1h, *w2h, *wnh, *temp, *baseh;
    float  *tb1f, *tb2f;
    cudaGetSymbolAddress((void**)&f0h,   g_f0h);
    cudaGetSymbolAddress((void**)&h1h,   g_h1h);
    cudaGetSymbolAddress((void**)&w1h,   g_w1h);
    cudaGetSymbolAddress((void**)&w2h,   g_w2h);
    cudaGetSymbolAddress((void**)&wnh,   g_wnh);
    cudaGetSymbolAddress((void**)&temp,  g_temp);
    cudaGetSymbolAddress((void**)&tb1f,  g_tb1f);
    cudaGetSymbolAddress((void**)&tb2f,  g_tb2f);
    cudaGetSymbolAddress((void**)&baseh, g_base2h);

    // 1-2: BN1 stats (+ p2t zero)
    k_bn_partial<CA><<<NBLK, 256>>>(feats);
    k_bn_finalize<CA, 0><<<1, 4 * CA>>>(bn1_gamma, bn1_beta);
    // 3: prep (f0h, fold w1, tb1, dummy rows, p2t scatter)
    k_prep1<<<NB_F0 + NB_W1 + NB_TBF + NB_MI + NB_MAP, 256>>>(feats, w1, sidx);
    // 4: conv1 compact GEMM (profiled slot)
    k_convc<CA><<<KOFF * TIL, 256, sm1>>>(f0h, w1h, tb1f, gidx, sidx, temp);
    // 5: reduce -> h1h (raw conv1, fp16)
    k_reduce<false><<<NV / 8, 256>>>(temp, nullptr, h1h);
    // 6-7: BN2 stats
    k_bn_partial_h<<<NBLK, 256>>>(h1h);
    k_bn_finalize<CB, 1><<<1, 4 * CB>>>(bn2_gamma, bn2_beta);
    // 8: prep2 (fold w2, tb2, wnh)
    k_prep2<<<NB_W2 + NB_TBF + NB_WN, 256>>>(w2, w_nin);
    // 9: skip GEMM (fp16 base)
    k_base2<<<TIL, 256, smb>>>(f0h, wnh, baseh);
    // 10: conv2 compact GEMM (pipelined 2-chunk)
    k_convc<CB><<<KOFF * TIL, 256, sm2>>>(h1h, w2h, tb2f, gidx, sidx, temp);
    // 11: final reduce -> out (fp32)
    k_reduce<true><<<NV / 8, 256>>>(temp, baseh, out);
}